// round 1
// baseline (speedup 1.0000x reference)
#include <cuda_runtime.h>
#include <cstdint>
#include <cstddef>

#define NB 8
#define NL 4096
#define ND 1024
#define NH 16
#define NT 64
#define NDFF 2048

// ---------------- scratch (static device arrays; no allocation) ----------------
__device__ float g_q[NT * ND];                       // 256 KB
__device__ float g_kv[(size_t)NB * NL * 2 * ND];     // 256 MB  (k | v per row)
__device__ float g_att[NB * NT * ND];                // 2 MB
__device__ float g_po[NB * NT * ND];                 // 2 MB
__device__ float g_h[(size_t)NB * NL * NDFF];        // 256 MB

// ---------------- helpers ----------------
__device__ __forceinline__ float f2tf(float x) {
    uint32_t u;
    asm("cvt.rna.tf32.f32 %0, %1;" : "=r"(u) : "f"(x));
    return __uint_as_float(u);
}

__device__ __forceinline__ void mma8(float* c, const uint32_t* a, uint32_t b0, uint32_t b1) {
    asm volatile(
        "mma.sync.aligned.m16n8k8.row.col.f32.tf32.tf32.f32 "
        "{%0,%1,%2,%3}, {%4,%5,%6,%7}, {%8,%9}, {%0,%1,%2,%3};\n"
        : "+f"(c[0]), "+f"(c[1]), "+f"(c[2]), "+f"(c[3])
        : "r"(a[0]), "r"(a[1]), "r"(a[2]), "r"(a[3]), "r"(b0), "r"(b1));
}

__device__ __forceinline__ float gelu_exact(float x) {
    return 0.5f * x * (1.0f + erff(x * 0.70710678118654752f));
}

// ---------------- generic TF32 GEMM:  C[M,N] = A[M,K] @ W[N,K]^T + bias ----------------
// AMODE 0: A is a plain row-major [M,K] matrix.
// AMODE 1: A is "compressed" [B*T, 1024]; row r of the logical A matrix is the
//          linear interpolation of compressed rows (F.interpolate semantics).
// ACT 1: exact GELU epilogue.
template<int AMODE, int ACT>
__global__ void __launch_bounds__(256, 1)
gemm_tn(const float* __restrict__ A, const float* __restrict__ W,
        const float* __restrict__ bias, float* __restrict__ C,
        int M, int N, int K)
{
    __shared__ float As[2][128][20];
    __shared__ float Bs[2][128][20];
    const int tid = threadIdx.x;
    const int wid = tid >> 5, lane = tid & 31;
    const int wm = wid & 3, wn = wid >> 2;       // 4 x 2 warp grid
    const int g = lane >> 2, t4 = lane & 3;
    const int rowBase = blockIdx.y << 7;
    const int colBase = blockIdx.x << 7;

    float acc[2][8][4];
#pragma unroll
    for (int i = 0; i < 2; i++)
#pragma unroll
        for (int j = 0; j < 8; j++)
#pragma unroll
            for (int k = 0; k < 4; k++) acc[i][j][k] = 0.f;

    const int KT = K >> 4;
    float4 pa[2], pb[2];

    auto loadT = [&](int kt) {
        const int k0 = kt << 4;
#pragma unroll
        for (int it = 0; it < 2; it++) {
            const int fi = tid + (it << 8);
            const int row = fi >> 2;
            const int cc = (fi & 3) << 2;
            float4 v = make_float4(0.f, 0.f, 0.f, 0.f);
            const int gr = rowBase + row;
            if (AMODE == 0) {
                if (gr < M) v = *(const float4*)(A + (size_t)gr * K + k0 + cc);
            } else {
                const int bb = gr >> 12, ll = gr & 4095;
                float pos = fminf(fmaxf((ll + 0.5f) * 0.015625f - 0.5f, 0.f), 63.f);
                const int i0 = (int)pos;
                const float fr = pos - (float)i0;
                const int i1 = min(i0 + 1, 63);
                const float4 v0 = *(const float4*)(A + (size_t)((bb << 6) + i0) * ND + k0 + cc);
                const float4 v1 = *(const float4*)(A + (size_t)((bb << 6) + i1) * ND + k0 + cc);
                v.x = v0.x * (1.f - fr) + v1.x * fr;
                v.y = v0.y * (1.f - fr) + v1.y * fr;
                v.z = v0.z * (1.f - fr) + v1.z * fr;
                v.w = v0.w * (1.f - fr) + v1.w * fr;
            }
            pa[it] = v;
            const int gn = colBase + row;
            float4 wv = make_float4(0.f, 0.f, 0.f, 0.f);
            if (gn < N) wv = *(const float4*)(W + (size_t)gn * K + k0 + cc);
            pb[it] = wv;
        }
    };
    auto storeT = [&](int buf) {
#pragma unroll
        for (int it = 0; it < 2; it++) {
            const int fi = tid + (it << 8);
            const int row = fi >> 2;
            const int cc = (fi & 3) << 2;
            As[buf][row][cc + 0] = f2tf(pa[it].x);
            As[buf][row][cc + 1] = f2tf(pa[it].y);
            As[buf][row][cc + 2] = f2tf(pa[it].z);
            As[buf][row][cc + 3] = f2tf(pa[it].w);
            Bs[buf][row][cc + 0] = f2tf(pb[it].x);
            Bs[buf][row][cc + 1] = f2tf(pb[it].y);
            Bs[buf][row][cc + 2] = f2tf(pb[it].z);
            Bs[buf][row][cc + 3] = f2tf(pb[it].w);
        }
    };

    loadT(0);
    storeT(0);
    __syncthreads();

    for (int kt = 0; kt < KT; kt++) {
        const int cur = kt & 1;
        const bool more = (kt + 1) < KT;
        if (more) loadT(kt + 1);
#pragma unroll
        for (int ks = 0; ks < 2; ks++) {
            const int kk = ks << 3;
            uint32_t af[2][4];
#pragma unroll
            for (int mi = 0; mi < 2; mi++) {
                const int r = (wm << 5) + (mi << 4);
                af[mi][0] = __float_as_uint(As[cur][r + g][kk + t4]);
                af[mi][1] = __float_as_uint(As[cur][r + 8 + g][kk + t4]);
                af[mi][2] = __float_as_uint(As[cur][r + g][kk + t4 + 4]);
                af[mi][3] = __float_as_uint(As[cur][r + 8 + g][kk + t4 + 4]);
            }
#pragma unroll
            for (int ni = 0; ni < 8; ni++) {
                const int cb = (wn << 6) + (ni << 3);
                const uint32_t b0 = __float_as_uint(Bs[cur][cb + g][kk + t4]);
                const uint32_t b1 = __float_as_uint(Bs[cur][cb + g][kk + t4 + 4]);
                mma8(acc[0][ni], af[0], b0, b1);
                mma8(acc[1][ni], af[1], b0, b1);
            }
        }
        if (more) storeT(cur ^ 1);
        __syncthreads();
    }

#pragma unroll
    for (int mi = 0; mi < 2; mi++) {
#pragma unroll
        for (int ni = 0; ni < 8; ni++) {
            const int r0 = rowBase + (wm << 5) + (mi << 4) + g;
            const int cc = colBase + (wn << 6) + (ni << 3) + (t4 << 1);
            const float b0v = bias[cc], b1v = bias[cc + 1];
            float x0 = acc[mi][ni][0] + b0v;
            float x1 = acc[mi][ni][1] + b1v;
            float x2 = acc[mi][ni][2] + b0v;
            float x3 = acc[mi][ni][3] + b1v;
            if (ACT) {
                x0 = gelu_exact(x0); x1 = gelu_exact(x1);
                x2 = gelu_exact(x2); x3 = gelu_exact(x3);
            }
            if (r0 < M) {
                C[(size_t)r0 * N + cc]     = x0;
                C[(size_t)r0 * N + cc + 1] = x1;
            }
            if (r0 + 8 < M) {
                C[(size_t)(r0 + 8) * N + cc]     = x2;
                C[(size_t)(r0 + 8) * N + cc + 1] = x3;
            }
        }
    }
}

// ---------------- flash attention per (b,h): q[64,64] x kv[L] ----------------
// grid = B*H (128), block = 128 threads (4 warps, each owns 16 query rows).
__global__ void __launch_bounds__(128, 1)
attn_kernel(const float* __restrict__ q, const float* __restrict__ kv,
            float* __restrict__ out)
{
    extern __shared__ float sm[];
    float* qs  = sm;                 // 64 * 68
    float* ksm = qs + 64 * 68;       // 128 * 68
    float* vsm = ksm + 128 * 68;     // 128 * 72
    float* psm = vsm + 128 * 72;     // 64 * 132

    const int tid = threadIdx.x;
    const int w = tid >> 5, lane = tid & 31;
    const int g = lane >> 2, t4 = lane & 3;
    const int b = blockIdx.x >> 4, h = blockIdx.x & 15;

    // load q tile (prescaled by 1/sqrt(hd) = 1/8, tf32-rounded)
#pragma unroll
    for (int it = 0; it < 8; it++) {
        const int fi = tid + (it << 7);
        const int row = fi >> 4, cc = (fi & 15) << 2;
        float4 v = *(const float4*)(q + row * ND + h * 64 + cc);
        qs[row * 68 + cc + 0] = f2tf(v.x * 0.125f);
        qs[row * 68 + cc + 1] = f2tf(v.y * 0.125f);
        qs[row * 68 + cc + 2] = f2tf(v.z * 0.125f);
        qs[row * 68 + cc + 3] = f2tf(v.w * 0.125f);
    }
    __syncthreads();

    const int qrb = w << 4;
    uint32_t qf[8][4];
#pragma unroll
    for (int k8 = 0; k8 < 8; k8++) {
        qf[k8][0] = __float_as_uint(qs[(qrb + g) * 68 + k8 * 8 + t4]);
        qf[k8][1] = __float_as_uint(qs[(qrb + 8 + g) * 68 + k8 * 8 + t4]);
        qf[k8][2] = __float_as_uint(qs[(qrb + g) * 68 + k8 * 8 + t4 + 4]);
        qf[k8][3] = __float_as_uint(qs[(qrb + 8 + g) * 68 + k8 * 8 + t4 + 4]);
    }

    float o[8][4];
#pragma unroll
    for (int i = 0; i < 8; i++)
#pragma unroll
        for (int j = 0; j < 4; j++) o[i][j] = 0.f;
    float m0 = -1e30f, m1 = -1e30f, l0 = 0.f, l1 = 0.f;

    const float* kvb = kv + (size_t)b * NL * 2048 + h * 64;

    for (int lt = 0; lt < NL / 128; lt++) {
        // load k & v tiles [128 x 64]
#pragma unroll
        for (int it = 0; it < 16; it++) {
            const int fi = tid + (it << 7);
            const int row = fi >> 4, cc = (fi & 15) << 2;
            const float* rp = kvb + (size_t)(lt * 128 + row) * 2048 + cc;
            float4 kk = *(const float4*)rp;
            float4 vv = *(const float4*)(rp + 1024);
            ksm[row * 68 + cc + 0] = f2tf(kk.x);
            ksm[row * 68 + cc + 1] = f2tf(kk.y);
            ksm[row * 68 + cc + 2] = f2tf(kk.z);
            ksm[row * 68 + cc + 3] = f2tf(kk.w);
            vsm[row * 72 + cc + 0] = f2tf(vv.x);
            vsm[row * 72 + cc + 1] = f2tf(vv.y);
            vsm[row * 72 + cc + 2] = f2tf(vv.z);
            vsm[row * 72 + cc + 3] = f2tf(vv.w);
        }
        __syncthreads();

        // s = q @ k^T  : [16 rows x 128 cols] per warp
        float s[16][4];
#pragma unroll
        for (int i = 0; i < 16; i++)
#pragma unroll
            for (int j = 0; j < 4; j++) s[i][j] = 0.f;
#pragma unroll
        for (int k8 = 0; k8 < 8; k8++) {
#pragma unroll
            for (int ni = 0; ni < 16; ni++) {
                const uint32_t b0 = __float_as_uint(ksm[(ni * 8 + g) * 68 + k8 * 8 + t4]);
                const uint32_t b1 = __float_as_uint(ksm[(ni * 8 + g) * 68 + k8 * 8 + t4 + 4]);
                mma8(s[ni], qf[k8], b0, b1);
            }
        }

        // online softmax
        float mx0 = -1e30f, mx1 = -1e30f;
#pragma unroll
        for (int ni = 0; ni < 16; ni++) {
            mx0 = fmaxf(mx0, fmaxf(s[ni][0], s[ni][1]));
            mx1 = fmaxf(mx1, fmaxf(s[ni][2], s[ni][3]));
        }
        mx0 = fmaxf(mx0, __shfl_xor_sync(0xffffffffu, mx0, 1));
        mx0 = fmaxf(mx0, __shfl_xor_sync(0xffffffffu, mx0, 2));
        mx1 = fmaxf(mx1, __shfl_xor_sync(0xffffffffu, mx1, 1));
        mx1 = fmaxf(mx1, __shfl_xor_sync(0xffffffffu, mx1, 2));
        const float mn0 = fmaxf(m0, mx0), mn1 = fmaxf(m1, mx1);
        const float al0 = __expf(m0 - mn0), al1 = __expf(m1 - mn1);
        float sum0 = 0.f, sum1 = 0.f;
#pragma unroll
        for (int ni = 0; ni < 16; ni++) {
            const float p0 = __expf(s[ni][0] - mn0);
            const float p1 = __expf(s[ni][1] - mn0);
            const float p2 = __expf(s[ni][2] - mn1);
            const float p3 = __expf(s[ni][3] - mn1);
            sum0 += p0 + p1;
            sum1 += p2 + p3;
            const int cc = ni * 8 + (t4 << 1);
            psm[(qrb + g) * 132 + cc]         = f2tf(p0);
            psm[(qrb + g) * 132 + cc + 1]     = f2tf(p1);
            psm[(qrb + 8 + g) * 132 + cc]     = f2tf(p2);
            psm[(qrb + 8 + g) * 132 + cc + 1] = f2tf(p3);
        }
        sum0 += __shfl_xor_sync(0xffffffffu, sum0, 1);
        sum0 += __shfl_xor_sync(0xffffffffu, sum0, 2);
        sum1 += __shfl_xor_sync(0xffffffffu, sum1, 1);
        sum1 += __shfl_xor_sync(0xffffffffu, sum1, 2);
        l0 = l0 * al0 + sum0;
        l1 = l1 * al1 + sum1;
        m0 = mn0; m1 = mn1;
#pragma unroll
        for (int ni = 0; ni < 8; ni++) {
            o[ni][0] *= al0; o[ni][1] *= al0;
            o[ni][2] *= al1; o[ni][3] *= al1;
        }
        __syncwarp();

        // o += p @ v  : K = 128
#pragma unroll
        for (int k8 = 0; k8 < 16; k8++) {
            uint32_t af[4];
            af[0] = __float_as_uint(psm[(qrb + g) * 132 + k8 * 8 + t4]);
            af[1] = __float_as_uint(psm[(qrb + 8 + g) * 132 + k8 * 8 + t4]);
            af[2] = __float_as_uint(psm[(qrb + g) * 132 + k8 * 8 + t4 + 4]);
            af[3] = __float_as_uint(psm[(qrb + 8 + g) * 132 + k8 * 8 + t4 + 4]);
#pragma unroll
            for (int ni = 0; ni < 8; ni++) {
                const uint32_t b0 = __float_as_uint(vsm[(k8 * 8 + t4) * 72 + ni * 8 + g]);
                const uint32_t b1 = __float_as_uint(vsm[(k8 * 8 + t4 + 4) * 72 + ni * 8 + g]);
                mma8(o[ni], af, b0, b1);
            }
        }
        __syncthreads();
    }

    const float i0v = 1.0f / l0, i1v = 1.0f / l1;
#pragma unroll
    for (int ni = 0; ni < 8; ni++) {
        const int t = qrb + g;
        const int d = h * 64 + ni * 8 + (t4 << 1);
        float* op = out + (size_t)(b * NT + t) * ND + d;
        op[0] = o[ni][0] * i0v;
        op[1] = o[ni][1] * i0v;
        float* op2 = out + (size_t)(b * NT + t + 8) * ND + d;
        op2[0] = o[ni][2] * i1v;
        op2[1] = o[ni][3] * i1v;
    }
}

// ---------------- LayerNorm over D=1024, one block per row ----------------
__global__ void __launch_bounds__(256, 1)
ln_kernel(const float* __restrict__ x, const float* __restrict__ gam,
          const float* __restrict__ bet, float* __restrict__ out)
{
    const int row = blockIdx.x, tid = threadIdx.x;
    const float4 v = ((const float4*)(x + (size_t)row * ND))[tid];
    float s = v.x + v.y + v.z + v.w;
    float ss = v.x * v.x + v.y * v.y + v.z * v.z + v.w * v.w;
#pragma unroll
    for (int off = 16; off; off >>= 1) {
        s  += __shfl_down_sync(0xffffffffu, s, off);
        ss += __shfl_down_sync(0xffffffffu, ss, off);
    }
    __shared__ float sb[8], sq[8];
    __shared__ float mu_s, rs_s;
    const int w = tid >> 5, lane = tid & 31;
    if (lane == 0) { sb[w] = s; sq[w] = ss; }
    __syncthreads();
    if (tid == 0) {
        float S = 0.f, SS = 0.f;
#pragma unroll
        for (int i = 0; i < 8; i++) { S += sb[i]; SS += sq[i]; }
        const float mu = S * (1.0f / 1024.0f);
        const float var = SS * (1.0f / 1024.0f) - mu * mu;
        mu_s = mu;
        rs_s = rsqrtf(var + 1e-5f);
    }
    __syncthreads();
    const float mu = mu_s, rs = rs_s;
    const float4 gv = ((const float4*)gam)[tid];
    const float4 bv = ((const float4*)bet)[tid];
    float4 r;
    r.x = (v.x - mu) * rs * gv.x + bv.x;
    r.y = (v.y - mu) * rs * gv.y + bv.y;
    r.z = (v.z - mu) * rs * gv.z + bv.z;
    r.w = (v.w - mu) * rs * gv.w + bv.w;
    ((float4*)(out + (size_t)row * ND))[tid] = r;
}

// ---------------- host launcher ----------------
extern "C" void kernel_launch(void* const* d_in, const int* in_sizes, int n_in,
                              void* d_out, int out_size) {
    (void)in_sizes; (void)n_in; (void)out_size;
    const float* memory = (const float*)d_in[0];
    const float* query  = (const float*)d_in[1];
    const float* in_w   = (const float*)d_in[2];
    const float* in_b   = (const float*)d_in[3];
    const float* ow     = (const float*)d_in[4];
    const float* ob     = (const float*)d_in[5];
    const float* lg     = (const float*)d_in[6];
    const float* lb     = (const float*)d_in[7];
    const float* w1     = (const float*)d_in[8];
    const float* b1     = (const float*)d_in[9];
    const float* w2     = (const float*)d_in[10];
    const float* b2     = (const float*)d_in[11];

    float* outp  = (float*)d_out;
    float* comp  = outp;                                  // [B,T,D]
    float* recon = outp + (size_t)NB * NT * ND;           // [B,L,D]

    float *pq, *pkv, *patt, *ppo, *ph;
    cudaGetSymbolAddress((void**)&pq,   g_q);
    cudaGetSymbolAddress((void**)&pkv,  g_kv);
    cudaGetSymbolAddress((void**)&patt, g_att);
    cudaGetSymbolAddress((void**)&ppo,  g_po);
    cudaGetSymbolAddress((void**)&ph,   g_h);

    cudaFuncSetAttribute(attn_kernel, cudaFuncAttributeMaxDynamicSharedMemorySize, 123 * 1024);

    const dim3 blk(256);

    // 1. q projection: [64,1024] @ Wq^T
    gemm_tn<0, 0><<<dim3(8, 1), blk>>>(query, in_w, in_b, pq, NT, ND, ND);

    // 2. fused K|V projection: [32768,1024] @ [Wk;Wv]^T -> [32768,2048]
    gemm_tn<0, 0><<<dim3(16, 256), blk>>>(memory, in_w + 1024 * 1024, in_b + 1024,
                                          pkv, NB * NL, 2 * ND, ND);

    // 3. flash attention per (b,h)
    attn_kernel<<<NB * NH, 128, 122880>>>(pq, pkv, patt);

    // 4. output projection [512,1024] @ Wout^T
    gemm_tn<0, 0><<<dim3(8, 4), blk>>>(patt, ow, ob, ppo, NB * NT, ND, ND);

    // 5. LayerNorm -> compressed (first output)
    ln_kernel<<<NB * NT, 256>>>(ppo, lg, lb, comp);

    // 6. MLP1 with fused linear interpolation + exact GELU: [32768,1024] @ w1^T -> [32768,2048]
    gemm_tn<1, 1><<<dim3(16, 256), blk>>>(comp, w1, b1, ph, NB * NL, NDFF, ND);

    // 7. MLP2: [32768,2048] @ w2^T -> recon (second output)
    gemm_tn<0, 0><<<dim3(8, 256), blk>>>(ph, w2, b2, recon, NB * NL, ND, NDFF);
}

// round 2
// speedup vs baseline: 1.4712x; 1.4712x over previous
#include <cuda_runtime.h>
#include <cstdint>
#include <cstddef>

#define NB 8
#define NL 4096
#define ND 1024
#define NH 16
#define NT 64
#define NDFF 2048

// ---------------- scratch (static device arrays; no allocation) ----------------
__device__ float g_q[NT * ND];                       // 256 KB
__device__ float g_kv[(size_t)NB * NL * 2 * ND];     // 256 MB  (k | v per row)
__device__ float g_att[NB * NT * ND];                // 2 MB
__device__ float g_po[NB * NT * ND];                 // 2 MB
__device__ float g_h[(size_t)NB * NL * NDFF];        // 256 MB
__device__ float g_mem[(size_t)NB * NL * ND];        // 128 MB (tf32-rounded memory)
__device__ float g_up[(size_t)NB * NL * ND];         // 128 MB (tf32-rounded interp)
__device__ float g_wkv[2 * ND * ND];                 // 8 MB  (rounded Wk|Wv)
__device__ float g_w1r[NDFF * ND];                   // 8 MB
__device__ float g_w2r[ND * NDFF];                   // 8 MB

// ---------------- helpers ----------------
__device__ __forceinline__ float f2tf(float x) {
    uint32_t u;
    asm("cvt.rna.tf32.f32 %0, %1;" : "=r"(u) : "f"(x));
    return __uint_as_float(u);
}

__device__ __forceinline__ void mma8(float* c, const uint32_t* a, uint32_t b0, uint32_t b1) {
    asm volatile(
        "mma.sync.aligned.m16n8k8.row.col.f32.tf32.tf32.f32 "
        "{%0,%1,%2,%3}, {%4,%5,%6,%7}, {%8,%9}, {%0,%1,%2,%3};\n"
        : "+f"(c[0]), "+f"(c[1]), "+f"(c[2]), "+f"(c[3])
        : "r"(a[0]), "r"(a[1]), "r"(a[2]), "r"(a[3]), "r"(b0), "r"(b1));
}

__device__ __forceinline__ void cp16(uint32_t s, const float* g) {
    asm volatile("cp.async.cg.shared.global [%0], [%1], 16;\n" :: "r"(s), "l"(g));
}
__device__ __forceinline__ void cp_commit() {
    asm volatile("cp.async.commit_group;\n" ::: "memory");
}
__device__ __forceinline__ void cp_wait2() {
    asm volatile("cp.async.wait_group 2;\n" ::: "memory");
}

__device__ __forceinline__ float gelu_exact(float x) {
    return 0.5f * x * (1.0f + erff(x * 0.70710678118654752f));
}

// ---------------- tf32 rounding pass ----------------
__global__ void round_k(const float4* __restrict__ in, float4* __restrict__ out, int n4) {
    int i = blockIdx.x * blockDim.x + threadIdx.x;
    if (i < n4) {
        float4 v = in[i];
        v.x = f2tf(v.x); v.y = f2tf(v.y); v.z = f2tf(v.z); v.w = f2tf(v.w);
        out[i] = v;
    }
}

// ---------------- linear interpolation (compressed[B,T,D] -> up[B,L,D], tf32-rounded) ----
__global__ void interp_k(const float* __restrict__ comp, float* __restrict__ up) {
    const int row = blockIdx.x;            // 0..B*L-1
    const int b = row >> 12, l = row & 4095;
    float pos = fminf(fmaxf((l + 0.5f) * 0.015625f - 0.5f, 0.f), 63.f);
    const int i0 = (int)pos;
    const float fr = pos - (float)i0;
    const int i1 = min(i0 + 1, 63);
    const float4 a = ((const float4*)(comp + (size_t)(b * 64 + i0) * ND))[threadIdx.x];
    const float4 c = ((const float4*)(comp + (size_t)(b * 64 + i1) * ND))[threadIdx.x];
    float4 o;
    o.x = f2tf(a.x * (1.f - fr) + c.x * fr);
    o.y = f2tf(a.y * (1.f - fr) + c.y * fr);
    o.z = f2tf(a.z * (1.f - fr) + c.z * fr);
    o.w = f2tf(a.w * (1.f - fr) + c.w * fr);
    ((float4*)(up + (size_t)row * ND))[threadIdx.x] = o;
}

// ---------------- big async GEMM:  C[M,N] = A[M,K] @ W[N,K]^T + bias ----------------
// Requires: M % 128 == 0, N % 128 == 0, K % 32 == 0, A/W pre-rounded to tf32.
// 4-stage cp.async pipeline, BM=BN=128, BK=32, 256 threads (4x2 warp grid, 32x64/warp).
#define STAGES 4
#define LDP 36                       // 32 + 4 pad floats
#define TILEF (128 * LDP)            // floats per A (or B) stage tile
#define STAGEF (2 * TILEF)           // floats per stage (A|B)
#define GSMEM_BYTES (STAGES * STAGEF * 4)

template<int ACT, int RND>
__global__ void __launch_bounds__(256, 1)
gemm_async(const float* __restrict__ A, const float* __restrict__ W,
           const float* __restrict__ bias, float* __restrict__ C,
           int M, int N, int K)
{
    extern __shared__ float smem[];
    const uint32_t smem_u = (uint32_t)__cvta_generic_to_shared(smem);

    const int tid = threadIdx.x;
    const int wid = tid >> 5, lane = tid & 31;
    const int wm = wid & 3, wn = wid >> 2;
    const int g = lane >> 2, t4 = lane & 3;
    const int rowBase = blockIdx.y << 7;
    const int colBase = blockIdx.x << 7;

    float acc[2][8][4];
#pragma unroll
    for (int i = 0; i < 2; i++)
#pragma unroll
        for (int j = 0; j < 8; j++)
#pragma unroll
            for (int k = 0; k < 4; k++) acc[i][j][k] = 0.f;

    const int KT = K >> 5;

    // per-thread copy assignment: 4 A chunks + 4 B chunks of 16B
    const int crow = tid >> 1;                 // base row pattern via idx = tid + i*256
    (void)crow;

    auto copyTile = [&](int kt, int slot) {
        const float* Ab = A + (size_t)rowBase * K + (kt << 5);
        const float* Bb = W + (size_t)colBase * K + (kt << 5);
        const uint32_t sa = smem_u + (uint32_t)slot * (STAGEF * 4);
        const uint32_t sb = sa + TILEF * 4;
#pragma unroll
        for (int i = 0; i < 4; i++) {
            const int idx = tid + (i << 8);    // 0..1023
            const int row = idx >> 3;
            const int ch = (idx & 7) << 2;     // float offset in k
            cp16(sa + (uint32_t)(row * LDP + ch) * 4, Ab + (size_t)row * K + ch);
            cp16(sb + (uint32_t)(row * LDP + ch) * 4, Bb + (size_t)row * K + ch);
        }
    };

#pragma unroll
    for (int s = 0; s < STAGES - 1; s++) {
        copyTile(s, s);
        cp_commit();
    }

    for (int kt = 0; kt < KT; kt++) {
        cp_wait2();
        __syncthreads();
        if (kt + STAGES - 1 < KT) copyTile(kt + STAGES - 1, (kt + STAGES - 1) & (STAGES - 1));
        cp_commit();

        const int slot = kt & (STAGES - 1);
        const float* As = smem + slot * STAGEF;
        const float* Bs = As + TILEF;

#pragma unroll
        for (int k8 = 0; k8 < 4; k8++) {
            const int kk = k8 << 3;
            uint32_t af[2][4];
#pragma unroll
            for (int mi = 0; mi < 2; mi++) {
                const int r = (wm << 5) + (mi << 4);
                af[mi][0] = __float_as_uint(As[(r + g) * LDP + kk + t4]);
                af[mi][1] = __float_as_uint(As[(r + 8 + g) * LDP + kk + t4]);
                af[mi][2] = __float_as_uint(As[(r + g) * LDP + kk + t4 + 4]);
                af[mi][3] = __float_as_uint(As[(r + 8 + g) * LDP + kk + t4 + 4]);
            }
#pragma unroll
            for (int ni = 0; ni < 8; ni++) {
                const int cb = (wn << 6) + (ni << 3);
                const uint32_t b0 = __float_as_uint(Bs[(cb + g) * LDP + kk + t4]);
                const uint32_t b1 = __float_as_uint(Bs[(cb + g) * LDP + kk + t4 + 4]);
                mma8(acc[0][ni], af[0], b0, b1);
                mma8(acc[1][ni], af[1], b0, b1);
            }
        }
    }

#pragma unroll
    for (int mi = 0; mi < 2; mi++) {
#pragma unroll
        for (int ni = 0; ni < 8; ni++) {
            const int r0 = rowBase + (wm << 5) + (mi << 4) + g;
            const int cc = colBase + (wn << 6) + (ni << 3) + (t4 << 1);
            const float b0v = bias[cc], b1v = bias[cc + 1];
            float x0 = acc[mi][ni][0] + b0v;
            float x1 = acc[mi][ni][1] + b1v;
            float x2 = acc[mi][ni][2] + b0v;
            float x3 = acc[mi][ni][3] + b1v;
            if (ACT) {
                x0 = gelu_exact(x0); x1 = gelu_exact(x1);
                x2 = gelu_exact(x2); x3 = gelu_exact(x3);
            }
            if (RND) {
                x0 = f2tf(x0); x1 = f2tf(x1); x2 = f2tf(x2); x3 = f2tf(x3);
            }
            C[(size_t)r0 * N + cc]           = x0;
            C[(size_t)r0 * N + cc + 1]       = x1;
            C[(size_t)(r0 + 8) * N + cc]     = x2;
            C[(size_t)(r0 + 8) * N + cc + 1] = x3;
        }
    }
}

// ---------------- small GEMM (legacy path, bounds-checked):  C = A @ W^T + bias --------
__global__ void __launch_bounds__(256, 1)
gemm_tn(const float* __restrict__ A, const float* __restrict__ W,
        const float* __restrict__ bias, float* __restrict__ C,
        int M, int N, int K)
{
    __shared__ float As[2][128][20];
    __shared__ float Bs[2][128][20];
    const int tid = threadIdx.x;
    const int wid = tid >> 5, lane = tid & 31;
    const int wm = wid & 3, wn = wid >> 2;
    const int g = lane >> 2, t4 = lane & 3;
    const int rowBase = blockIdx.y << 7;
    const int colBase = blockIdx.x << 7;

    float acc[2][8][4];
#pragma unroll
    for (int i = 0; i < 2; i++)
#pragma unroll
        for (int j = 0; j < 8; j++)
#pragma unroll
            for (int k = 0; k < 4; k++) acc[i][j][k] = 0.f;

    const int KT = K >> 4;
    float4 pa[2], pb[2];

    auto loadT = [&](int kt) {
        const int k0 = kt << 4;
#pragma unroll
        for (int it = 0; it < 2; it++) {
            const int fi = tid + (it << 8);
            const int row = fi >> 2;
            const int cc = (fi & 3) << 2;
            float4 v = make_float4(0.f, 0.f, 0.f, 0.f);
            const int gr = rowBase + row;
            if (gr < M) v = *(const float4*)(A + (size_t)gr * K + k0 + cc);
            pa[it] = v;
            const int gn = colBase + row;
            float4 wv = make_float4(0.f, 0.f, 0.f, 0.f);
            if (gn < N) wv = *(const float4*)(W + (size_t)gn * K + k0 + cc);
            pb[it] = wv;
        }
    };
    auto storeT = [&](int buf) {
#pragma unroll
        for (int it = 0; it < 2; it++) {
            const int fi = tid + (it << 8);
            const int row = fi >> 2;
            const int cc = (fi & 3) << 2;
            As[buf][row][cc + 0] = f2tf(pa[it].x);
            As[buf][row][cc + 1] = f2tf(pa[it].y);
            As[buf][row][cc + 2] = f2tf(pa[it].z);
            As[buf][row][cc + 3] = f2tf(pa[it].w);
            Bs[buf][row][cc + 0] = f2tf(pb[it].x);
            Bs[buf][row][cc + 1] = f2tf(pb[it].y);
            Bs[buf][row][cc + 2] = f2tf(pb[it].z);
            Bs[buf][row][cc + 3] = f2tf(pb[it].w);
        }
    };

    loadT(0);
    storeT(0);
    __syncthreads();

    for (int kt = 0; kt < KT; kt++) {
        const int cur = kt & 1;
        const bool more = (kt + 1) < KT;
        if (more) loadT(kt + 1);
#pragma unroll
        for (int ks = 0; ks < 2; ks++) {
            const int kk = ks << 3;
            uint32_t af[2][4];
#pragma unroll
            for (int mi = 0; mi < 2; mi++) {
                const int r = (wm << 5) + (mi << 4);
                af[mi][0] = __float_as_uint(As[cur][r + g][kk + t4]);
                af[mi][1] = __float_as_uint(As[cur][r + 8 + g][kk + t4]);
                af[mi][2] = __float_as_uint(As[cur][r + g][kk + t4 + 4]);
                af[mi][3] = __float_as_uint(As[cur][r + 8 + g][kk + t4 + 4]);
            }
#pragma unroll
            for (int ni = 0; ni < 8; ni++) {
                const int cb = (wn << 6) + (ni << 3);
                const uint32_t b0 = __float_as_uint(Bs[cur][cb + g][kk + t4]);
                const uint32_t b1 = __float_as_uint(Bs[cur][cb + g][kk + t4 + 4]);
                mma8(acc[0][ni], af[0], b0, b1);
                mma8(acc[1][ni], af[1], b0, b1);
            }
        }
        if (more) storeT(cur ^ 1);
        __syncthreads();
    }

#pragma unroll
    for (int mi = 0; mi < 2; mi++) {
#pragma unroll
        for (int ni = 0; ni < 8; ni++) {
            const int r0 = rowBase + (wm << 5) + (mi << 4) + g;
            const int cc = colBase + (wn << 6) + (ni << 3) + (t4 << 1);
            const float b0v = bias[cc], b1v = bias[cc + 1];
            float x0 = acc[mi][ni][0] + b0v;
            float x1 = acc[mi][ni][1] + b1v;
            float x2 = acc[mi][ni][2] + b0v;
            float x3 = acc[mi][ni][3] + b1v;
            if (r0 < M) {
                C[(size_t)r0 * N + cc]     = x0;
                C[(size_t)r0 * N + cc + 1] = x1;
            }
            if (r0 + 8 < M) {
                C[(size_t)(r0 + 8) * N + cc]     = x2;
                C[(size_t)(r0 + 8) * N + cc + 1] = x3;
            }
        }
    }
}

// ---------------- flash attention per (b,h): q[64,64] x kv[L] ----------------
__global__ void __launch_bounds__(128, 1)
attn_kernel(const float* __restrict__ q, const float* __restrict__ kv,
            float* __restrict__ out)
{
    extern __shared__ float sm[];
    float* qs  = sm;                 // 64 * 68
    float* ksm = qs + 64 * 68;       // 128 * 68
    float* vsm = ksm + 128 * 68;     // 128 * 72
    float* psm = vsm + 128 * 72;     // 64 * 132

    const int tid = threadIdx.x;
    const int w = tid >> 5, lane = tid & 31;
    const int g = lane >> 2, t4 = lane & 3;
    const int b = blockIdx.x >> 4, h = blockIdx.x & 15;

#pragma unroll
    for (int it = 0; it < 8; it++) {
        const int fi = tid + (it << 7);
        const int row = fi >> 4, cc = (fi & 15) << 2;
        float4 v = *(const float4*)(q + row * ND + h * 64 + cc);
        qs[row * 68 + cc + 0] = f2tf(v.x * 0.125f);
        qs[row * 68 + cc + 1] = f2tf(v.y * 0.125f);
        qs[row * 68 + cc + 2] = f2tf(v.z * 0.125f);
        qs[row * 68 + cc + 3] = f2tf(v.w * 0.125f);
    }
    __syncthreads();

    const int qrb = w << 4;
    uint32_t qf[8][4];
#pragma unroll
    for (int k8 = 0; k8 < 8; k8++) {
        qf[k8][0] = __float_as_uint(qs[(qrb + g) * 68 + k8 * 8 + t4]);
        qf[k8][1] = __float_as_uint(qs[(qrb + 8 + g) * 68 + k8 * 8 + t4]);
        qf[k8][2] = __float_as_uint(qs[(qrb + g) * 68 + k8 * 8 + t4 + 4]);
        qf[k8][3] = __float_as_uint(qs[(qrb + 8 + g) * 68 + k8 * 8 + t4 + 4]);
    }

    float o[8][4];
#pragma unroll
    for (int i = 0; i < 8; i++)
#pragma unroll
        for (int j = 0; j < 4; j++) o[i][j] = 0.f;
    float m0 = -1e30f, m1 = -1e30f, l0 = 0.f, l1 = 0.f;

    const float* kvb = kv + (size_t)b * NL * 2048 + h * 64;

    for (int lt = 0; lt < NL / 128; lt++) {
#pragma unroll
        for (int it = 0; it < 16; it++) {
            const int fi = tid + (it << 7);
            const int row = fi >> 4, cc = (fi & 15) << 2;
            const float* rp = kvb + (size_t)(lt * 128 + row) * 2048 + cc;
            float4 kk = *(const float4*)rp;
            float4 vv = *(const float4*)(rp + 1024);
            ksm[row * 68 + cc + 0] = f2tf(kk.x);
            ksm[row * 68 + cc + 1] = f2tf(kk.y);
            ksm[row * 68 + cc + 2] = f2tf(kk.z);
            ksm[row * 68 + cc + 3] = f2tf(kk.w);
            vsm[row * 72 + cc + 0] = f2tf(vv.x);
            vsm[row * 72 + cc + 1] = f2tf(vv.y);
            vsm[row * 72 + cc + 2] = f2tf(vv.z);
            vsm[row * 72 + cc + 3] = f2tf(vv.w);
        }
        __syncthreads();

        float s[16][4];
#pragma unroll
        for (int i = 0; i < 16; i++)
#pragma unroll
            for (int j = 0; j < 4; j++) s[i][j] = 0.f;
#pragma unroll
        for (int k8 = 0; k8 < 8; k8++) {
#pragma unroll
            for (int ni = 0; ni < 16; ni++) {
                const uint32_t b0 = __float_as_uint(ksm[(ni * 8 + g) * 68 + k8 * 8 + t4]);
                const uint32_t b1 = __float_as_uint(ksm[(ni * 8 + g) * 68 + k8 * 8 + t4 + 4]);
                mma8(s[ni], qf[k8], b0, b1);
            }
        }

        float mx0 = -1e30f, mx1 = -1e30f;
#pragma unroll
        for (int ni = 0; ni < 16; ni++) {
            mx0 = fmaxf(mx0, fmaxf(s[ni][0], s[ni][1]));
            mx1 = fmaxf(mx1, fmaxf(s[ni][2], s[ni][3]));
        }
        mx0 = fmaxf(mx0, __shfl_xor_sync(0xffffffffu, mx0, 1));
        mx0 = fmaxf(mx0, __shfl_xor_sync(0xffffffffu, mx0, 2));
        mx1 = fmaxf(mx1, __shfl_xor_sync(0xffffffffu, mx1, 1));
        mx1 = fmaxf(mx1, __shfl_xor_sync(0xffffffffu, mx1, 2));
        const float mn0 = fmaxf(m0, mx0), mn1 = fmaxf(m1, mx1);
        const float al0 = __expf(m0 - mn0), al1 = __expf(m1 - mn1);
        float sum0 = 0.f, sum1 = 0.f;
#pragma unroll
        for (int ni = 0; ni < 16; ni++) {
            const float p0 = __expf(s[ni][0] - mn0);
            const float p1 = __expf(s[ni][1] - mn0);
            const float p2 = __expf(s[ni][2] - mn1);
            const float p3 = __expf(s[ni][3] - mn1);
            sum0 += p0 + p1;
            sum1 += p2 + p3;
            const int cc = ni * 8 + (t4 << 1);
            psm[(qrb + g) * 132 + cc]         = f2tf(p0);
            psm[(qrb + g) * 132 + cc + 1]     = f2tf(p1);
            psm[(qrb + 8 + g) * 132 + cc]     = f2tf(p2);
            psm[(qrb + 8 + g) * 132 + cc + 1] = f2tf(p3);
        }
        sum0 += __shfl_xor_sync(0xffffffffu, sum0, 1);
        sum0 += __shfl_xor_sync(0xffffffffu, sum0, 2);
        sum1 += __shfl_xor_sync(0xffffffffu, sum1, 1);
        sum1 += __shfl_xor_sync(0xffffffffu, sum1, 2);
        l0 = l0 * al0 + sum0;
        l1 = l1 * al1 + sum1;
        m0 = mn0; m1 = mn1;
#pragma unroll
        for (int ni = 0; ni < 8; ni++) {
            o[ni][0] *= al0; o[ni][1] *= al0;
            o[ni][2] *= al1; o[ni][3] *= al1;
        }
        __syncwarp();

#pragma unroll
        for (int k8 = 0; k8 < 16; k8++) {
            uint32_t af[4];
            af[0] = __float_as_uint(psm[(qrb + g) * 132 + k8 * 8 + t4]);
            af[1] = __float_as_uint(psm[(qrb + 8 + g) * 132 + k8 * 8 + t4]);
            af[2] = __float_as_uint(psm[(qrb + g) * 132 + k8 * 8 + t4 + 4]);
            af[3] = __float_as_uint(psm[(qrb + 8 + g) * 132 + k8 * 8 + t4 + 4]);
#pragma unroll
            for (int ni = 0; ni < 8; ni++) {
                const uint32_t b0 = __float_as_uint(vsm[(k8 * 8 + t4) * 72 + ni * 8 + g]);
                const uint32_t b1 = __float_as_uint(vsm[(k8 * 8 + t4 + 4) * 72 + ni * 8 + g]);
                mma8(o[ni], af, b0, b1);
            }
        }
        __syncthreads();
    }

    const float i0v = 1.0f / l0, i1v = 1.0f / l1;
#pragma unroll
    for (int ni = 0; ni < 8; ni++) {
        const int t = qrb + g;
        const int d = h * 64 + ni * 8 + (t4 << 1);
        float* op = out + (size_t)(b * NT + t) * ND + d;
        op[0] = o[ni][0] * i0v;
        op[1] = o[ni][1] * i0v;
        float* op2 = out + (size_t)(b * NT + t + 8) * ND + d;
        op2[0] = o[ni][2] * i1v;
        op2[1] = o[ni][3] * i1v;
    }
}

// ---------------- LayerNorm over D=1024, one block per row ----------------
__global__ void __launch_bounds__(256, 1)
ln_kernel(const float* __restrict__ x, const float* __restrict__ gam,
          const float* __restrict__ bet, float* __restrict__ out)
{
    const int row = blockIdx.x, tid = threadIdx.x;
    const float4 v = ((const float4*)(x + (size_t)row * ND))[tid];
    float s = v.x + v.y + v.z + v.w;
    float ss = v.x * v.x + v.y * v.y + v.z * v.z + v.w * v.w;
#pragma unroll
    for (int off = 16; off; off >>= 1) {
        s  += __shfl_down_sync(0xffffffffu, s, off);
        ss += __shfl_down_sync(0xffffffffu, ss, off);
    }
    __shared__ float sb[8], sq[8];
    __shared__ float mu_s, rs_s;
    const int w = tid >> 5, lane = tid & 31;
    if (lane == 0) { sb[w] = s; sq[w] = ss; }
    __syncthreads();
    if (tid == 0) {
        float S = 0.f, SS = 0.f;
#pragma unroll
        for (int i = 0; i < 8; i++) { S += sb[i]; SS += sq[i]; }
        const float mu = S * (1.0f / 1024.0f);
        const float var = SS * (1.0f / 1024.0f) - mu * mu;
        mu_s = mu;
        rs_s = rsqrtf(var + 1e-5f);
    }
    __syncthreads();
    const float mu = mu_s, rs = rs_s;
    const float4 gv = ((const float4*)gam)[tid];
    const float4 bv = ((const float4*)bet)[tid];
    float4 r;
    r.x = (v.x - mu) * rs * gv.x + bv.x;
    r.y = (v.y - mu) * rs * gv.y + bv.y;
    r.z = (v.z - mu) * rs * gv.z + bv.z;
    r.w = (v.w - mu) * rs * gv.w + bv.w;
    ((float4*)(out + (size_t)row * ND))[tid] = r;
}

// ---------------- host launcher ----------------
extern "C" void kernel_launch(void* const* d_in, const int* in_sizes, int n_in,
                              void* d_out, int out_size) {
    (void)in_sizes; (void)n_in; (void)out_size;
    const float* memory = (const float*)d_in[0];
    const float* query  = (const float*)d_in[1];
    const float* in_w   = (const float*)d_in[2];
    const float* in_b   = (const float*)d_in[3];
    const float* ow     = (const float*)d_in[4];
    const float* ob     = (const float*)d_in[5];
    const float* lg     = (const float*)d_in[6];
    const float* lb     = (const float*)d_in[7];
    const float* w1     = (const float*)d_in[8];
    const float* b1     = (const float*)d_in[9];
    const float* w2     = (const float*)d_in[10];
    const float* b2     = (const float*)d_in[11];

    float* outp  = (float*)d_out;
    float* comp  = outp;                                  // [B,T,D]
    float* recon = outp + (size_t)NB * NT * ND;           // [B,L,D]

    float *pq, *pkv, *patt, *ppo, *ph, *pmem, *pup, *pwkv, *pw1, *pw2;
    cudaGetSymbolAddress((void**)&pq,   g_q);
    cudaGetSymbolAddress((void**)&pkv,  g_kv);
    cudaGetSymbolAddress((void**)&patt, g_att);
    cudaGetSymbolAddress((void**)&ppo,  g_po);
    cudaGetSymbolAddress((void**)&ph,   g_h);
    cudaGetSymbolAddress((void**)&pmem, g_mem);
    cudaGetSymbolAddress((void**)&pup,  g_up);
    cudaGetSymbolAddress((void**)&pwkv, g_wkv);
    cudaGetSymbolAddress((void**)&pw1,  g_w1r);
    cudaGetSymbolAddress((void**)&pw2,  g_w2r);

    cudaFuncSetAttribute(attn_kernel, cudaFuncAttributeMaxDynamicSharedMemorySize, 123 * 1024);
    cudaFuncSetAttribute(gemm_async<0, 0>, cudaFuncAttributeMaxDynamicSharedMemorySize, GSMEM_BYTES);
    cudaFuncSetAttribute(gemm_async<1, 1>, cudaFuncAttributeMaxDynamicSharedMemorySize, GSMEM_BYTES);

    const dim3 blk(256);

    // 0. tf32 pre-rounding passes
    {
        int n4 = (NB * NL * ND) / 4;
        round_k<<<(n4 + 255) / 256, 256>>>((const float4*)memory, (float4*)pmem, n4);
        n4 = (2 * ND * ND) / 4;
        round_k<<<(n4 + 255) / 256, 256>>>((const float4*)(in_w + ND * ND), (float4*)pwkv, n4);
        n4 = (NDFF * ND) / 4;
        round_k<<<(n4 + 255) / 256, 256>>>((const float4*)w1, (float4*)pw1, n4);
        round_k<<<(n4 + 255) / 256, 256>>>((const float4*)w2, (float4*)pw2, n4);
    }

    // 1. q projection: [64,1024] @ Wq^T (small, legacy path)
    gemm_tn<<<dim3(8, 1), blk>>>(query, in_w, in_b, pq, NT, ND, ND);

    // 2. fused K|V projection: [32768,1024] @ [Wk;Wv]^T -> [32768,2048]
    gemm_async<0, 0><<<dim3(16, 256), blk, GSMEM_BYTES>>>(pmem, pwkv, in_b + ND, pkv,
                                                          NB * NL, 2 * ND, ND);

    // 3. flash attention per (b,h)
    attn_kernel<<<NB * NH, 128, 122880>>>(pq, pkv, patt);

    // 4. output projection [512,1024] @ Wout^T (small, legacy path)
    gemm_tn<<<dim3(8, 4), blk>>>(patt, ow, ob, ppo, NB * NT, ND, ND);

    // 5. LayerNorm -> compressed (first output)
    ln_kernel<<<NB * NT, 256>>>(ppo, lg, lb, comp);

    // 6. interpolate compressed -> up (rounded)
    interp_k<<<NB * NL, 256>>>(comp, pup);

    // 7. MLP1 + exact GELU (round output for MLP2): [32768,1024] @ w1^T -> [32768,2048]
    gemm_async<1, 1><<<dim3(16, 256), blk, GSMEM_BYTES>>>(pup, pw1, b1, ph,
                                                          NB * NL, NDFF, ND);

    // 8. MLP2: [32768,2048] @ w2^T -> recon (second output)
    gemm_async<0, 0><<<dim3(8, 256), blk, GSMEM_BYTES>>>(ph, pw2, b2, recon,
                                                         NB * NL, ND, NDFF);
}